// round 15
// baseline (speedup 1.0000x reference)
#include <cuda_runtime.h>
#include <cuda_bf16.h>
#include <math.h>
#include <stdint.h>

#define N_NODES 10000
#define N_EDGES 320000
#define IN_DIM  10000
#define HID     128
#define NCLS    2

// ---------------- scratch (no allocs allowed) --------------------------------
__device__ float g_h[(size_t)N_NODES * HID];     // x @ W_conv (atomic-accumulated)
__device__ float g_agg[(size_t)N_NODES * HID];   // aggregated messages (edges only)
__device__ float g_deg[N_NODES];                 // 1 + sum of incoming edge weights
__device__ int   g_is32;                         // edge_index dtype flag
__device__ signed char g_Wb1[(size_t)HID * IN_DIM];  // W^T hi int8 slice (scale 2^-11)
__device__ signed char g_Wb0[(size_t)HID * IN_DIM];  // W^T lo int8 slice (scale 2^-19)

// ---------------- helpers ----------------------------------------------------
__device__ __forceinline__ uint32_t smem_u32(const void* p) {
    uint32_t a;
    asm("{ .reg .u64 t; cvta.to.shared.u64 t, %1; cvt.u32.u64 %0, t; }"
        : "=r"(a) : "l"(p));
    return a;
}

#define LDSM4(r, addr)                                                         \
    asm volatile("ldmatrix.sync.aligned.m8n8.x4.shared.b16 {%0,%1,%2,%3}, [%4];" \
                 : "=r"((r)[0]), "=r"((r)[1]), "=r"((r)[2]), "=r"((r)[3])      \
                 : "r"(addr))

// int8 MMA: D(s32) += A(s8,row) * B(s8,col); byte layout identical to bf16 k16.
#define IMMA16832(d, a, b0_, b1_)                                              \
    asm volatile("mma.sync.aligned.m16n8k32.row.col.s32.s8.s8.s32 "            \
                 "{%0,%1,%2,%3}, {%4,%5,%6,%7}, {%8,%9}, {%0,%1,%2,%3};"       \
                 : "+r"((d)[0]), "+r"((d)[1]), "+r"((d)[2]), "+r"((d)[3])      \
                 : "r"((a)[0]), "r"((a)[1]), "r"((a)[2]), "r"((a)[3]),         \
                   "r"(b0_), "r"(b1_))

__device__ __forceinline__ int clamp8(int v) {
    return v < -127 ? -127 : (v > 127 ? 127 : v);
}

// ---------------- prep: W int8 split + zero g_h/g_agg + deg=1 + detect -------
#define WSPLIT_BLOCKS 1252
__global__ __launch_bounds__(256) void k_prep(const float* __restrict__ W,
                                              const long long* ei) {
    __shared__ float t[32][33];
    int bid = blockIdx.x;
    if (bid < WSPLIT_BLOCKS) {
        int kb = (bid % 313) * 32, nb = (bid / 313) * 32;
        int tx = threadIdx.x & 31, ty = threadIdx.x >> 5;   // ty 0..7
#pragma unroll
        for (int r = ty; r < 32; r += 8) {
            int k = kb + r;
            t[r][tx] = (k < IN_DIM) ? W[(size_t)k * HID + nb + tx] : 0.0f;
        }
        __syncthreads();
#pragma unroll
        for (int r = ty; r < 32; r += 8) {
            int n = nb + r;
            int k = kb + tx;
            if (k < IN_DIM) {
                float v  = t[tx][r];
                float t1 = rintf(v * 2048.0f);               // slice 1: scale 2^-11
                float r0 = fmaf(t1, -256.0f, v * 524288.0f); // residual * 2^19
                int i1 = clamp8((int)t1);
                int i0 = clamp8((int)rintf(r0));
                g_Wb1[(size_t)n * IN_DIM + k] = (signed char)i1;
                g_Wb0[(size_t)n * IN_DIM + k] = (signed char)i0;
            }
        }
    } else {
        int i = (bid - WSPLIT_BLOCKS) * 256 + threadIdx.x;
        if (i < (N_NODES * HID) / 4) {
            ((float4*)g_h)[i]   = make_float4(0.f, 0.f, 0.f, 0.f);
            ((float4*)g_agg)[i] = make_float4(0.f, 0.f, 0.f, 0.f);
        }
        if (i < N_NODES) g_deg[i] = 1.0f;   // self-loop weight
        if (i == 0) {
            int is32 = 0;
            for (int j = 0; j < 16; j++) {
                long long v = ei[j];
                if (v < 0 || v >= N_NODES) { is32 = 1; break; }
            }
            g_is32 = is32;
        }
    }
}
__device__ __forceinline__ int edge_idx(const void* ei, long long i) {
    if (g_is32) return ((const int*)ei)[i];
    return (int)((const long long*)ei)[i];
}

__global__ void k_deg_accum(const void* ei, const float* __restrict__ ew) {
    int e = blockIdx.x * blockDim.x + threadIdx.x;
    if (e < N_EDGES) {
        int c = edge_idx(ei, (long long)N_EDGES + e);
        atomicAdd(&g_deg[c], ew[e]);
    }
}

// ---------------- IMMA GEMM: h = x @ W_conv (int8 3-term split, K-split x9) --
// x = a1/2^4 + a0/2^12 (int8 slices; |x|<7.94 covered), w = b1/2^11 + b0/2^19.
// h = S11/2^15 + (S10+S01)/2^23 ; a0*b0 (2^-31) dropped (~2.5e-4 rel).
// BM=128, BN=128, BK=64 floats; 512 threads = 16 warps 4x4; warptile 32x32.
// m16n8k32.s8 has identical byte-level fragments to m16n8k16.bf16 -> same
// ldmatrix addressing; k-steps per chunk 4 -> 2 (half the MMA instructions).
#define BM 128
#define BN 128
#define BK 64
#define STRB 80                         // row stride in BYTES (64 data + 16 pad)
#define NCHT ((IN_DIM + BK - 1) / BK)   // 157 total chunks
#define KSPL 9
#define CPS  ((NCHT + KSPL - 1) / KSPL) // 18 chunks per split
#define ABLK (BM * STRB)                // 10240 B per (buf,slice) block
#define GSMEM (8 * ABLK)                // 81920 B total (A:4 blocks, B:4 blocks)

__global__ __launch_bounds__(512, 1) void k_gemm_mma(const float* __restrict__ x) {
    extern __shared__ __align__(16) char smem[];
#define SAp(buf, sl) (smem + ((buf) * 2 + (sl)) * ABLK)
#define SBp(buf, sl) (smem + (4 + (buf) * 2 + (sl)) * ABLK)

    const int tid  = threadIdx.x;
    const int lane = tid & 31;
    const int wid  = tid >> 5;
    const int wm   = wid >> 2;          // 0..3
    const int wn   = wid & 3;           // 0..3
    const int m0   = blockIdx.y * BM;
    const int cs   = blockIdx.x * CPS;
    const int ce   = min(cs + CPS, NCHT);
    const int nch  = ce - cs;

    int s11[2][4][4], smid[2][4][4];
#pragma unroll
    for (int a = 0; a < 2; a++)
#pragma unroll
        for (int b = 0; b < 4; b++)
#pragma unroll
            for (int c = 0; c < 4; c++) { s11[a][b][c] = 0; smid[a][b][c] = 0; }

    float4 pa[4];

// A tile: 128 rows x 64 floats; 512 threads x 4 iters (row = q>>4, group q&15).
#define LOADGA(cc)                                                             \
    {                                                                          \
        const int k0 = (cc) * BK;                                              \
        _Pragma("unroll")                                                      \
        for (int i = 0; i < 4; i++) {                                          \
            int q = tid + 512 * i, row = q >> 4, c4 = q & 15;                  \
            int gm = m0 + row, k = k0 + c4 * 4;                                \
            pa[i] = (gm < N_NODES && k < IN_DIM)                               \
                        ? *(const float4*)(x + (size_t)gm * IN_DIM + k)        \
                        : make_float4(0.f, 0.f, 0.f, 0.f);                     \
        }                                                                      \
    }

// quantize one float -> (hi, lo) int8 pair
#define QSPLIT(v, i1, i0)                                                      \
    {                                                                          \
        float t1 = rintf((v) * 16.0f);                                         \
        float r0 = fmaf(t1, -256.0f, (v) * 4096.0f);                           \
        i1 = clamp8((int)t1);                                                  \
        i0 = clamp8((int)rintf(r0));                                           \
    }

#define STORESA(p)                                                             \
    {                                                                          \
        _Pragma("unroll")                                                      \
        for (int i = 0; i < 4; i++) {                                          \
            int q = tid + 512 * i, row = q >> 4, c4 = q & 15;                  \
            float4 v = pa[i];                                                  \
            int h0, l0, h1, l1, h2, l2, h3, l3;                                \
            QSPLIT(v.x, h0, l0); QSPLIT(v.y, h1, l1);                          \
            QSPLIT(v.z, h2, l2); QSPLIT(v.w, h3, l3);                          \
            uint32_t uh = (uint32_t)(h0 & 255) | ((uint32_t)(h1 & 255) << 8) | \
                          ((uint32_t)(h2 & 255) << 16) | ((uint32_t)h3 << 24); \
            uint32_t ul = (uint32_t)(l0 & 255) | ((uint32_t)(l1 & 255) << 8) | \
                          ((uint32_t)(l2 & 255) << 16) | ((uint32_t)l3 << 24); \
            *(uint32_t*)(SAp(p, 0) + row * STRB + c4 * 4) = uh;                \
            *(uint32_t*)(SAp(p, 1) + row * STRB + c4 * 4) = ul;                \
        }                                                                      \
    }

// B tile: 128 rows x 64 int8 per slice = 512 x 16B; one cp per thread per slice.
#define CPB(p, cc)                                                             \
    {                                                                          \
        int row = tid >> 2, seg = tid & 3;                                     \
        int k = (cc) * BK + seg * 16;                                          \
        uint32_t d1 = smem_u32(SBp(p, 0) + row * STRB + seg * 16);             \
        uint32_t d0 = smem_u32(SBp(p, 1) + row * STRB + seg * 16);             \
        if (k + 16 <= IN_DIM) {                                                \
            const void* s1 = g_Wb1 + (size_t)row * IN_DIM + k;                 \
            const void* s0 = g_Wb0 + (size_t)row * IN_DIM + k;                 \
            asm volatile("cp.async.ca.shared.global [%0], [%1], 16;"           \
                         :: "r"(d1), "l"(s1));                                 \
            asm volatile("cp.async.ca.shared.global [%0], [%1], 16;"           \
                         :: "r"(d0), "l"(s0));                                 \
        } else {                                                               \
            uint4 z = make_uint4(0, 0, 0, 0);                                  \
            *(uint4*)(SBp(p, 0) + row * STRB + seg * 16) = z;                  \
            *(uint4*)(SBp(p, 1) + row * STRB + seg * 16) = z;                  \
        }                                                                      \
        asm volatile("cp.async.commit_group;");                                \
    }

// one k32 step: load a1,a0,b1 frags; S11 += a1*b1, Smid += a0*b1;
// reload b frags with b0; Smid += a1*b0.  (peak 24 fragment regs)
#define KSTEP(ks)                                                              \
    {                                                                          \
        uint32_t a1f[2][4], a0f[2][4], bf[2][4];                               \
        _Pragma("unroll")                                                      \
        for (int mi = 0; mi < 2; mi++) {                                       \
            uint32_t off = (uint32_t)((wm * 32 + mi * 16 + lr) * STRB) +       \
                           (ks) * 32 + lc * 16;                                \
            LDSM4(a1f[mi], aS1 + off);                                         \
            LDSM4(a0f[mi], aS0 + off);                                         \
        }                                                                      \
        _Pragma("unroll")                                                      \
        for (int g = 0; g < 2; g++) {                                          \
            uint32_t off = (uint32_t)((wn * 32 + g * 16 + lr) * STRB) +        \
                           (ks) * 32 + lc * 16;                                \
            LDSM4(bf[g], bS1 + off);                                           \
        }                                                                      \
        _Pragma("unroll")                                                      \
        for (int mi = 0; mi < 2; mi++)                                         \
            _Pragma("unroll")                                                  \
            for (int ni = 0; ni < 4; ni++) {                                   \
                int g = ni >> 1, h = ni & 1;                                   \
                IMMA16832(s11[mi][ni], a1f[mi], bf[g][h], bf[g][h + 2]);       \
            }                                                                  \
        _Pragma("unroll")                                                      \
        for (int mi = 0; mi < 2; mi++)                                         \
            _Pragma("unroll")                                                  \
            for (int ni = 0; ni < 4; ni++) {                                   \
                int g = ni >> 1, h = ni & 1;                                   \
                IMMA16832(smid[mi][ni], a0f[mi], bf[g][h], bf[g][h + 2]);      \
            }                                                                  \
        _Pragma("unroll")                                                      \
        for (int g = 0; g < 2; g++) {                                          \
            uint32_t off = (uint32_t)((wn * 32 + g * 16 + lr) * STRB) +        \
                           (ks) * 32 + lc * 16;                                \
            LDSM4(bf[g], bS0 + off);                                           \
        }                                                                      \
        _Pragma("unroll")                                                      \
        for (int mi = 0; mi < 2; mi++)                                         \
            _Pragma("unroll")                                                  \
            for (int ni = 0; ni < 4; ni++) {                                   \
                int g = ni >> 1, h = ni & 1;                                   \
                IMMA16832(smid[mi][ni], a1f[mi], bf[g][h], bf[g][h + 2]);      \
            }                                                                  \
    }

    // prologue
    LOADGA(cs);
    STORESA(0);
    CPB(0, cs);
    LOADGA(cs + 1);
    asm volatile("cp.async.wait_group 0;" ::: "memory");
    __syncthreads();

    const int lr = lane & 15;
    const int lc = lane >> 4;

    for (int ci = 0; ci < nch; ci++) {
        const int p = ci & 1;
        const uint32_t aS1 = smem_u32(SAp(p, 0));
        const uint32_t aS0 = smem_u32(SAp(p, 1));
        const uint32_t bS1 = smem_u32(SBp(p, 0));
        const uint32_t bS0 = smem_u32(SBp(p, 1));

        KSTEP(0);

        // mid-chunk feed (overlaps other warps' MMAs)
        if (ci + 1 < nch) { STORESA((ci + 1) & 1); CPB((ci + 1) & 1, cs + ci + 1); }
        if (ci + 2 < nch) LOADGA(cs + ci + 2);

        KSTEP(1);

        asm volatile("cp.async.wait_group 0;" ::: "memory");
        __syncthreads();
    }

    // epilogue: combine scales, atomic-accumulate into g_h
    const float C1 = 3.0517578125e-5f;   // 2^-15
    const float C2 = 1.1920928955078125e-7f; // 2^-23
#pragma unroll
    for (int mi = 0; mi < 2; mi++) {
#pragma unroll
        for (int half = 0; half < 2; half++) {
            int row = m0 + wm * 32 + mi * 16 + (lane >> 2) + half * 8;
            if (row < N_NODES) {
#pragma unroll
                for (int ni = 0; ni < 4; ni++) {
                    int col = wn * 32 + ni * 8 + (lane & 3) * 2;
                    float v0 = (float)s11[mi][ni][2 * half] * C1 +
                               (float)smid[mi][ni][2 * half] * C2;
                    float v1 = (float)s11[mi][ni][2 * half + 1] * C1 +
                               (float)smid[mi][ni][2 * half + 1] * C2;
                    float* hp = g_h + (size_t)row * HID + col;
                    asm volatile("red.global.add.v2.f32 [%0], {%1, %2};"
                                 :: "l"(hp), "f"(v0), "f"(v1) : "memory");
                }
            }
        }
    }
#undef LOADGA
#undef STORESA
#undef CPB
#undef KSTEP
#undef QSPLIT
#undef SAp
#undef SBp
}

// ---------------- edge scatter: one warp per edge, vector RED ----------------
__global__ __launch_bounds__(256) void k_scatter(const void* ei,
                                                 const float* __restrict__ ew) {
    int gw   = blockIdx.x * 8 + (threadIdx.x >> 5);
    int lane = threadIdx.x & 31;
    if (gw >= N_EDGES) return;
    int r = edge_idx(ei, gw);                          // row (source)
    int c = edge_idx(ei, (long long)N_EDGES + gw);     // col (dest)
    float w = rsqrtf(g_deg[r]) * ew[gw] * rsqrtf(g_deg[c]);
    float4 v = ((const float4*)(g_h + (size_t)r * HID))[lane];
    float* ap = g_agg + (size_t)c * HID + lane * 4;
    asm volatile("red.global.add.v4.f32 [%0], {%1, %2, %3, %4};"
                 :: "l"(ap), "f"(w * v.x), "f"(w * v.y), "f"(w * v.z), "f"(w * v.w)
                 : "memory");
}

// ---------------- head: relu(agg + dinv^2*h + b_conv) @ W_lin, softmax -------
__global__ __launch_bounds__(256) void k_head(const float* __restrict__ b_conv,
                                              const float* __restrict__ W_lin,
                                              const float* __restrict__ b_lin,
                                              float* __restrict__ out) {
    int i    = blockIdx.x * 8 + (threadIdx.x >> 5);
    int lane = threadIdx.x & 31;
    if (i >= N_NODES) return;

    float dr = rsqrtf(g_deg[i]);
    float d2 = dr * dr;
    float4 v  = ((const float4*)(g_agg + (size_t)i * HID))[lane];
    float4 hv = ((const float4*)(g_h   + (size_t)i * HID))[lane];
    float4 b  = ((const float4*)b_conv)[lane];
    v.x = fmaxf(v.x + d2 * hv.x + b.x, 0.0f);
    v.y = fmaxf(v.y + d2 * hv.y + b.y, 0.0f);
    v.z = fmaxf(v.z + d2 * hv.z + b.z, 0.0f);
    v.w = fmaxf(v.w + d2 * hv.w + b.w, 0.0f);

    int k = lane * 4;
    float l0 = v.x * W_lin[(k + 0) * 2 + 0] + v.y * W_lin[(k + 1) * 2 + 0] +
               v.z * W_lin[(k + 2) * 2 + 0] + v.w * W_lin[(k + 3) * 2 + 0];
    float l1 = v.x * W_lin[(k + 0) * 2 + 1] + v.y * W_lin[(k + 1) * 2 + 1] +
               v.z * W_lin[(k + 2) * 2 + 1] + v.w * W_lin[(k + 3) * 2 + 1];

#pragma unroll
    for (int off = 16; off > 0; off >>= 1) {
        l0 += __shfl_xor_sync(0xFFFFFFFFu, l0, off);
        l1 += __shfl_xor_sync(0xFFFFFFFFu, l1, off);
    }

    if (lane == 0) {
        l0 += b_lin[0];
        l1 += b_lin[1];
        float m  = fmaxf(l0, l1);
        float e0 = expf(l0 - m), e1 = expf(l1 - m);
        float s  = e0 + e1;
        out[i * 2 + 0] = e0 / s;
        out[i * 2 + 1] = e1 / s;
    }
}

// -----------------------------------------------------------------------------
extern "C" void kernel_launch(void* const* d_in, const int* in_sizes, int n_in,
                              void* d_out, int out_size) {
    const float* x      = (const float*)d_in[0];
    const void*  ei     = d_in[1];                  // int64 or int32 (detected)
    const float* ew     = (const float*)d_in[2];
    const float* W_conv = (const float*)d_in[3];
    const float* b_conv = (const float*)d_in[4];
    const float* W_lin  = (const float*)d_in[5];
    const float* b_lin  = (const float*)d_in[6];
    float* out = (float*)d_out;

    cudaFuncSetAttribute(k_gemm_mma, cudaFuncAttributeMaxDynamicSharedMemorySize,
                         GSMEM);

    k_prep<<<WSPLIT_BLOCKS + 1250, 256>>>(W_conv, (const long long*)ei);
    k_deg_accum<<<(N_EDGES + 255) / 256, 256>>>(ei, ew);
    dim3 gg(KSPL, (N_NODES + BM - 1) / BM);       // (9, 79) = 711 CTAs
    k_gemm_mma<<<gg, 512, GSMEM>>>(x);
    k_scatter<<<(N_EDGES + 7) / 8, 256>>>(ei, ew);
    k_head<<<(N_NODES + 7) / 8, 256>>>(b_conv, W_lin, b_lin, out);
}

// round 17
// speedup vs baseline: 2.2189x; 2.2189x over previous
#include <cuda_runtime.h>
#include <cuda_bf16.h>
#include <math.h>
#include <stdint.h>

#define N_NODES 10000
#define N_EDGES 320000
#define IN_DIM  10000
#define HID     128
#define NCLS    2

// ---------------- scratch (no allocs allowed) --------------------------------
// All three accumulators rely on: (a) CUDA zero-initialization of __device__
// globals at module load, (b) k_head restoring them to zero at the end of
// every execution (it is the last kernel and reads every line anyway).
__device__ float g_h[(size_t)N_NODES * HID];     // x @ W_conv (atomic-accumulated)
__device__ float g_agg[(size_t)N_NODES * HID];   // aggregated messages (edges only)
__device__ float g_deg[N_NODES];                 // sum of incoming edge weights (no +1)
__device__ int   g_is32;                         // edge_index dtype flag
__device__ __nv_bfloat16 g_Wt_hi[(size_t)HID * IN_DIM];  // W^T hi split [128][10000]
__device__ __nv_bfloat16 g_Wt_lo[(size_t)HID * IN_DIM];  // W^T lo split

// ---------------- helpers ----------------------------------------------------
__device__ __forceinline__ uint32_t smem_u32(const void* p) {
    uint32_t a;
    asm("{ .reg .u64 t; cvta.to.shared.u64 t, %1; cvt.u32.u64 %0, t; }"
        : "=r"(a) : "l"(p));
    return a;
}

#define LDSM4(r, addr)                                                         \
    asm volatile("ldmatrix.sync.aligned.m8n8.x4.shared.b16 {%0,%1,%2,%3}, [%4];" \
                 : "=r"((r)[0]), "=r"((r)[1]), "=r"((r)[2]), "=r"((r)[3])      \
                 : "r"(addr))

#define MMA16816(d, a, b0, b1)                                                 \
    asm volatile("mma.sync.aligned.m16n8k16.row.col.f32.bf16.bf16.f32 "        \
                 "{%0,%1,%2,%3}, {%4,%5,%6,%7}, {%8,%9}, {%0,%1,%2,%3};"       \
                 : "+f"((d)[0]), "+f"((d)[1]), "+f"((d)[2]), "+f"((d)[3])      \
                 : "r"((a)[0]), "r"((a)[1]), "r"((a)[2]), "r"((a)[3]),         \
                   "r"(b0), "r"(b1))

__device__ __forceinline__ int detect_is32(const long long* ei) {
    int is32 = 0;
#pragma unroll
    for (int j = 0; j < 16; j++) {
        long long v = ei[j];
        if (v < 0 || v >= N_NODES) { is32 = 1; break; }
    }
    return is32;
}
__device__ __forceinline__ int edge_idx_f(const void* ei, long long i, int is32) {
    if (is32) return ((const int*)ei)[i];
    return (int)((const long long*)ei)[i];
}

// ---------------- prep: W bf16 split + deg accumulation + dtype publish ------
// Blocks [0, 1252): W transpose + hi/lo split.
// Blocks [1252, 2502): deg atomics (local dtype detect; g_deg starts at 0).
#define WSPLIT_BLOCKS 1252
#define DEG_BLOCKS    ((N_EDGES + 255) / 256)    // 1250
__global__ __launch_bounds__(256) void k_prep(const float* __restrict__ W,
                                              const long long* ei,
                                              const float* __restrict__ ew) {
    int bid = blockIdx.x;
    if (bid < WSPLIT_BLOCKS) {
        __shared__ float t[32][33];
        int kb = (bid % 313) * 32, nb = (bid / 313) * 32;
        int tx = threadIdx.x & 31, ty = threadIdx.x >> 5;   // ty 0..7
#pragma unroll
        for (int r = ty; r < 32; r += 8) {
            int k = kb + r;
            t[r][tx] = (k < IN_DIM) ? W[(size_t)k * HID + nb + tx] : 0.0f;
        }
        __syncthreads();
#pragma unroll
        for (int r = ty; r < 32; r += 8) {
            int n = nb + r;
            int k = kb + tx;
            if (k < IN_DIM) {
                float v = t[tx][r];
                __nv_bfloat16 hi = __float2bfloat16(v);
                __nv_bfloat16 lo = __float2bfloat16(v - __bfloat162float(hi));
                g_Wt_hi[(size_t)n * IN_DIM + k] = hi;
                g_Wt_lo[(size_t)n * IN_DIM + k] = lo;
            }
        }
        if (bid == 0 && threadIdx.x == 0) g_is32 = detect_is32(ei);  // for later kernels
    } else {
        __shared__ int s_is32;
        if (threadIdx.x == 0) s_is32 = detect_is32(ei);
        __syncthreads();
        int e = (bid - WSPLIT_BLOCKS) * 256 + threadIdx.x;
        if (e < N_EDGES) {
            int c = edge_idx_f(ei, (long long)N_EDGES + e, s_is32);
            atomicAdd(&g_deg[c], ew[e]);
        }
    }
}

// ---------------- HMMA GEMM: h = x @ W_conv (bf16x3 split, K-split x9) -------
// BM=128, BN=128, BK=64; 512 threads = 16 warps in 4x4; warptile 32x32.
// At the SIMT HMMA issue-rate floor (~512 MAC/cyc/SM); feed fully overlapped.
#define BM 128
#define BN 128
#define BK 64
#define STR 72                          // padded smem row stride (144 B)
#define NCHT ((IN_DIM + BK - 1) / BK)   // 157 total chunks
#define KSPL 9
#define CPS  ((NCHT + KSPL - 1) / KSPL) // 18 chunks per split
#define ABLK (BM * STR * 2)             // 18432 B per (buf,dt) block
#define GSMEM (8 * ABLK)                // 147456 B total

__global__ __launch_bounds__(512, 1) void k_gemm_mma(const float* __restrict__ x) {
    extern __shared__ __align__(16) char smem[];
#define SAp(buf, dt) ((__nv_bfloat16*)(smem + ((buf) * 2 + (dt)) * ABLK))
#define SBp(buf, dt) ((__nv_bfloat16*)(smem + (4 + (buf) * 2 + (dt)) * ABLK))

    const int tid  = threadIdx.x;
    const int lane = tid & 31;
    const int wid  = tid >> 5;
    const int wm   = wid >> 2;          // 0..3
    const int wn   = wid & 3;           // 0..3
    const int m0   = blockIdx.y * BM;
    const int cs   = blockIdx.x * CPS;
    const int ce   = min(cs + CPS, NCHT);
    const int nch  = ce - cs;

    float acc[2][4][4];
#pragma unroll
    for (int a = 0; a < 2; a++)
#pragma unroll
        for (int b = 0; b < 4; b++)
#pragma unroll
            for (int c = 0; c < 4; c++) acc[a][b][c] = 0.0f;

    float4 pa[4];

#define LOADGA(cc)                                                             \
    {                                                                          \
        const int k0 = (cc) * BK;                                              \
        _Pragma("unroll")                                                      \
        for (int i = 0; i < 4; i++) {                                          \
            int q = tid + 512 * i, row = q >> 4, c4 = q & 15;                  \
            int gm = m0 + row, k = k0 + c4 * 4;                                \
            pa[i] = (gm < N_NODES && k < IN_DIM)                               \
                        ? *(const float4*)(x + (size_t)gm * IN_DIM + k)        \
                        : make_float4(0.f, 0.f, 0.f, 0.f);                     \
        }                                                                      \
    }

#define STORESA(p)                                                             \
    {                                                                          \
        _Pragma("unroll")                                                      \
        for (int i = 0; i < 4; i++) {                                          \
            int q = tid + 512 * i, row = q >> 4, c4 = q & 15;                  \
            float4 v = pa[i];                                                  \
            __nv_bfloat162 h0 = __float22bfloat162_rn(make_float2(v.x, v.y));  \
            __nv_bfloat162 h1 = __float22bfloat162_rn(make_float2(v.z, v.w));  \
            float2 f0 = __bfloat1622float2(h0), f1 = __bfloat1622float2(h1);   \
            __nv_bfloat162 l0 = __float22bfloat162_rn(                         \
                make_float2(v.x - f0.x, v.y - f0.y));                          \
            __nv_bfloat162 l1 = __float22bfloat162_rn(                         \
                make_float2(v.z - f1.x, v.w - f1.y));                          \
            uint2 hh = make_uint2(*(uint32_t*)&h0, *(uint32_t*)&h1);           \
            uint2 ll = make_uint2(*(uint32_t*)&l0, *(uint32_t*)&l1);           \
            *(uint2*)(SAp(p, 0) + row * STR + c4 * 4) = hh;                    \
            *(uint2*)(SAp(p, 1) + row * STR + c4 * 4) = ll;                    \
        }                                                                      \
    }

#define CPB(p, cc)                                                             \
    {                                                                          \
        int row = tid >> 2, c4 = tid & 3;                                      \
        _Pragma("unroll")                                                      \
        for (int g2 = 0; g2 < 2; g2++) {                                       \
            int grp = c4 + g2 * 4;                                             \
            int k = (cc) * BK + grp * 8;                                       \
            if (k + 8 <= IN_DIM) {                                             \
                uint32_t dh = smem_u32(SBp(p, 0) + row * STR + grp * 8);       \
                uint32_t dl = smem_u32(SBp(p, 1) + row * STR + grp * 8);       \
                const void* sh = g_Wt_hi + (size_t)row * IN_DIM + k;           \
                const void* sl = g_Wt_lo + (size_t)row * IN_DIM + k;           \
                asm volatile("cp.async.ca.shared.global [%0], [%1], 16;"       \
                             :: "r"(dh), "l"(sh));                             \
                asm volatile("cp.async.ca.shared.global [%0], [%1], 16;"       \
                             :: "r"(dl), "l"(sl));                             \
            } else {                                                           \
                uint4 z = make_uint4(0, 0, 0, 0);                              \
                *(uint4*)(SBp(p, 0) + row * STR + grp * 8) = z;                \
                *(uint4*)(SBp(p, 1) + row * STR + grp * 8) = z;                \
            }                                                                  \
        }                                                                      \
        asm volatile("cp.async.commit_group;");                                \
    }

#define FRAGS(ks)                                                              \
    {                                                                          \
        _Pragma("unroll")                                                      \
        for (int mi = 0; mi < 2; mi++) {                                       \
            uint32_t off = (uint32_t)((wm * 32 + mi * 16 + lr) * STR) * 2 +    \
                           (ks) * 32 + lc * 16;                                \
            LDSM4(ah[mi], aHi + off);                                          \
            LDSM4(al[mi], aLo + off);                                          \
        }                                                                      \
        _Pragma("unroll")                                                      \
        for (int g = 0; g < 2; g++) {                                          \
            uint32_t off = (uint32_t)((wn * 32 + g * 16 + lr) * STR) * 2 +     \
                           (ks) * 32 + lc * 16;                                \
            LDSM4(bh[g], bHi + off);                                           \
            LDSM4(bl[g], bLo + off);                                           \
        }                                                                      \
    }

#define MMAS()                                                                 \
    {                                                                          \
        _Pragma("unroll")                                                      \
        for (int mi = 0; mi < 2; mi++)                                         \
            _Pragma("unroll")                                                  \
            for (int ni = 0; ni < 4; ni++) {                                   \
                int g = ni >> 1, h = ni & 1;                                   \
                MMA16816(acc[mi][ni], ah[mi], bh[g][h], bh[g][h + 2]);         \
            }                                                                  \
        _Pragma("unroll")                                                      \
        for (int mi = 0; mi < 2; mi++)                                         \
            _Pragma("unroll")                                                  \
            for (int ni = 0; ni < 4; ni++) {                                   \
                int g = ni >> 1, h = ni & 1;                                   \
                MMA16816(acc[mi][ni], ah[mi], bl[g][h], bl[g][h + 2]);         \
            }                                                                  \
        _Pragma("unroll")                                                      \
        for (int mi = 0; mi < 2; mi++)                                         \
            _Pragma("unroll")                                                  \
            for (int ni = 0; ni < 4; ni++) {                                   \
                int g = ni >> 1, h = ni & 1;                                   \
                MMA16816(acc[mi][ni], al[mi], bh[g][h], bh[g][h + 2]);         \
            }                                                                  \
    }

    // prologue
    LOADGA(cs);
    STORESA(0);
    CPB(0, cs);
    LOADGA(cs + 1);
    asm volatile("cp.async.wait_group 0;" ::: "memory");
    __syncthreads();

    const int lr = lane & 15;
    const int lc = lane >> 4;

    for (int ci = 0; ci < nch; ci++) {
        const int p = ci & 1;
        const uint32_t aHi = smem_u32(SAp(p, 0));
        const uint32_t aLo = smem_u32(SAp(p, 1));
        const uint32_t bHi = smem_u32(SBp(p, 0));
        const uint32_t bLo = smem_u32(SBp(p, 1));

        uint32_t ah[2][4], al[2][4], bh[2][4], bl[2][4];

        FRAGS(0);
        MMAS();
        FRAGS(1);
        MMAS();

        // mid-chunk feed (overlaps other warps' MMAs)
        if (ci + 1 < nch) { STORESA((ci + 1) & 1); CPB((ci + 1) & 1, cs + ci + 1); }
        if (ci + 2 < nch) LOADGA(cs + ci + 2);

        FRAGS(2);
        MMAS();
        FRAGS(3);
        MMAS();

        asm volatile("cp.async.wait_group 0;" ::: "memory");
        __syncthreads();
    }

    // epilogue: atomic-accumulate partial sums into g_h (zeroed by prior head)
#pragma unroll
    for (int mi = 0; mi < 2; mi++) {
#pragma unroll
        for (int half = 0; half < 2; half++) {
            int row = m0 + wm * 32 + mi * 16 + (lane >> 2) + half * 8;
            if (row < N_NODES) {
#pragma unroll
                for (int ni = 0; ni < 4; ni++) {
                    int col = wn * 32 + ni * 8 + (lane & 3) * 2;
                    float v0 = acc[mi][ni][2 * half];
                    float v1 = acc[mi][ni][2 * half + 1];
                    float* hp = g_h + (size_t)row * HID + col;
                    asm volatile("red.global.add.v2.f32 [%0], {%1, %2};"
                                 :: "l"(hp), "f"(v0), "f"(v1) : "memory");
                }
            }
        }
    }
#undef LOADGA
#undef STORESA
#undef CPB
#undef FRAGS
#undef MMAS
#undef SAp
#undef SBp
}

// ---------------- edge scatter: grid-stride, one warp per edge ---------------
#define SC_BLOCKS 2960
__global__ __launch_bounds__(256) void k_scatter(const void* ei,
                                                 const float* __restrict__ ew) {
    const int is32 = g_is32;
    int lane = threadIdx.x & 31;
    for (int gw = blockIdx.x * 8 + (threadIdx.x >> 5); gw < N_EDGES;
         gw += SC_BLOCKS * 8) {
        int r = edge_idx_f(ei, gw, is32);                      // row (source)
        int c = edge_idx_f(ei, (long long)N_EDGES + gw, is32); // col (dest)
        float w = rsqrtf(g_deg[r] + 1.0f) * ew[gw] * rsqrtf(g_deg[c] + 1.0f);
        float4 v = ((const float4*)(g_h + (size_t)r * HID))[lane];
        float* ap = g_agg + (size_t)c * HID + lane * 4;
        asm volatile("red.global.add.v4.f32 [%0], {%1, %2, %3, %4};"
                     :: "l"(ap), "f"(w * v.x), "f"(w * v.y), "f"(w * v.z),
                        "f"(w * v.w)
                     : "memory");
    }
}

// ---------------- head: relu(agg + h/(deg+1) + b_conv) @ W_lin, softmax ------
// Also restores g_h / g_agg / g_deg to zero for the next graph replay.
__global__ __launch_bounds__(256) void k_head(const float* __restrict__ b_conv,
                                              const float* __restrict__ W_lin,
                                              const float* __restrict__ b_lin,
                                              float* __restrict__ out) {
    int i    = blockIdx.x * 8 + (threadIdx.x >> 5);
    int lane = threadIdx.x & 31;
    if (i >= N_NODES) return;

    float d2 = 1.0f / (g_deg[i] + 1.0f);
    float4* aggp = (float4*)(g_agg + (size_t)i * HID) + lane;
    float4* hp   = (float4*)(g_h   + (size_t)i * HID) + lane;
    float4 v  = *aggp;
    float4 hv = *hp;
    float4 b  = ((const float4*)b_conv)[lane];
    v.x = fmaxf(v.x + d2 * hv.x + b.x, 0.0f);
    v.y = fmaxf(v.y + d2 * hv.y + b.y, 0.0f);
    v.z = fmaxf(v.z + d2 * hv.z + b.z, 0.0f);
    v.w = fmaxf(v.w + d2 * hv.w + b.w, 0.0f);

    // restore zeros for next execution (graph replay invariant)
    float4 z = make_float4(0.f, 0.f, 0.f, 0.f);
    *aggp = z;
    *hp   = z;
    if (lane == 0) g_deg[i] = 0.0f;

    int k = lane * 4;
    float l0 = v.x * W_lin[(k + 0) * 2 + 0] + v.y * W_lin[(k + 1) * 2 + 0] +
               v.z * W_lin[(k + 2) * 2 + 0] + v.w * W_lin[(k + 3) * 2 + 0];
    float l1 = v.x * W_lin[(k + 0) * 2 + 1] + v.y * W_lin[(k + 1) * 2 + 1] +
               v.z * W_lin[(k + 2) * 2 + 1] + v.w * W_lin[(k + 3) * 2 + 1];

#pragma unroll
    for (int off = 16; off > 0; off >>= 1) {
        l0 += __shfl_xor_sync(0xFFFFFFFFu, l0, off);
        l1 += __shfl_xor_sync(0xFFFFFFFFu, l1, off);
    }

    if (lane == 0) {
        l0 += b_lin[0];
        l1 += b_lin[1];
        float m  = fmaxf(l0, l1);
        float e0 = expf(l0 - m), e1 = expf(l1 - m);
        float s  = e0 + e1;
        out[i * 2 + 0] = e0 / s;
        out[i * 2 + 1] = e1 / s;
    }
}

// -----------------------------------------------------------------------------
extern "C" void kernel_launch(void* const* d_in, const int* in_sizes, int n_in,
                              void* d_out, int out_size) {
    const float* x      = (const float*)d_in[0];
    const void*  ei     = d_in[1];                  // int64 or int32 (detected)
    const float* ew     = (const float*)d_in[2];
    const float* W_conv = (const float*)d_in[3];
    const float* b_conv = (const float*)d_in[4];
    const float* W_lin  = (const float*)d_in[5];
    const float* b_lin  = (const float*)d_in[6];
    float* out = (float*)d_out;

    cudaFuncSetAttribute(k_gemm_mma, cudaFuncAttributeMaxDynamicSharedMemorySize,
                         GSMEM);

    k_prep<<<WSPLIT_BLOCKS + DEG_BLOCKS, 256>>>(W_conv, (const long long*)ei, ew);
    dim3 gg(KSPL, (N_NODES + BM - 1) / BM);       // (9, 79) = 711 CTAs
    k_gemm_mma<<<gg, 512, GSMEM>>>(x);
    k_scatter<<<SC_BLOCKS, 256>>>(ei, ew);
    k_head<<<(N_NODES + 7) / 8, 256>>>(b_conv, W_lin, b_lin, out);
}